// round 15
// baseline (speedup 1.0000x reference)
#include <cuda_runtime.h>
#include <cuda_bf16.h>
#include <cstdint>

// Problem constants
#define BB 16
#define TT 64
#define SS 256
#define DD 512

// Scratch (device globals — no allocations allowed)
__device__ float g_wq[BB * TT * DD];          // (B,T,D)   2 MB
__device__ float g_uh[BB * SS * DD];          // (B,S,D)   8 MB
__device__ float g_cc[BB * TT * DD];          // c only (B,T,D) 2 MB (tf32-rounded)
__device__ float g_s2[BB * TT * DD];          // src @ Ws^T partial 2 MB
// tf32-pre-rounded copies of GEMM inputs
__device__ float g_rsrc[BB * TT * DD];        // 2 MB
__device__ float g_rmem[BB * SS * DD];        // 8 MB
__device__ float g_rwq[DD * DD];              // 1 MB
__device__ float g_rwc[DD * DD];              // 1 MB
__device__ float g_rwout[DD * 2 * DD];        // 2 MB

__device__ __forceinline__ float htanh(float x) {
    float y;
    asm("tanh.approx.f32 %0, %1;" : "=f"(y) : "f"(x));
    return y;
}
__device__ __forceinline__ uint32_t to_tf32(float x) {
    uint32_t r;
    asm("cvt.rna.tf32.f32 %0, %1;" : "=r"(r) : "f"(x));
    return r;
}
__device__ __forceinline__ void mma_tf32(float* d, const uint32_t* a, const uint32_t* b) {
    asm volatile(
        "mma.sync.aligned.m16n8k8.row.col.f32.tf32.tf32.f32 "
        "{%0,%1,%2,%3}, {%4,%5,%6,%7}, {%8,%9}, {%0,%1,%2,%3};"
        : "+f"(d[0]), "+f"(d[1]), "+f"(d[2]), "+f"(d[3])
        : "r"(a[0]), "r"(a[1]), "r"(a[2]), "r"(a[3]), "r"(b[0]), "r"(b[1]));
}
__device__ __forceinline__ uint32_t cvta_sh(const void* p) {
    uint32_t a;
    asm("{ .reg .u64 t; cvta.to.shared.u64 t, %1; cvt.u32.u64 %0, t; }"
        : "=r"(a) : "l"(p));
    return a;
}
__device__ __forceinline__ void cp16(uint32_t dst, const void* src) {
    asm volatile("cp.async.cg.shared.global [%0], [%1], 16;"
                 :: "r"(dst), "l"(src) : "memory");
}
#define CP_COMMIT() asm volatile("cp.async.commit_group;" ::: "memory")
template <int N> __device__ __forceinline__ void cp_wait();
template <> __device__ __forceinline__ void cp_wait<1>() {
    asm volatile("cp.async.wait_group 1;" ::: "memory");
}
template <> __device__ __forceinline__ void cp_wait<2>() {
    asm volatile("cp.async.wait_group 2;" ::: "memory");
}

// ---------------------------------------------------------------------------
// Pre-round pass: flat 1D grid, exact block count (3584 x 256).
// ---------------------------------------------------------------------------
__global__ __launch_bounds__(256)
void round_kernel(const float* __restrict__ src, const float* __restrict__ mem,
                  const float* __restrict__ Wq, const float* __restrict__ Wc,
                  const float* __restrict__ Wout,
                  float* __restrict__ rsrc, float* __restrict__ rmem,
                  float* __restrict__ rwq, float* __restrict__ rwc,
                  float* __restrict__ rwout) {
    int i = blockIdx.x * 256 + threadIdx.x;
    const float* in;
    float* outp;
    int off;
    if (i < 131072)      { in = src;  outp = rsrc;  off = 0; }
    else if (i < 655360) { in = mem;  outp = rmem;  off = 131072; }
    else if (i < 720896) { in = Wq;   outp = rwq;   off = 655360; }
    else if (i < 786432) { in = Wc;   outp = rwc;   off = 720896; }
    else                 { in = Wout; outp = rwout; off = 786432; }
    int j = i - off;
    float4 v = *(const float4*)(in + (size_t)j * 4);
    float4 o;
    o.x = __uint_as_float(to_tf32(v.x));
    o.y = __uint_as_float(to_tf32(v.y));
    o.z = __uint_as_float(to_tf32(v.z));
    o.w = __uint_as_float(to_tf32(v.w));
    *(float4*)(outp + (size_t)j * 4) = o;
}

// ---------------------------------------------------------------------------
// tf32 mma.sync GEMM on pre-rounded inputs: C = A(M x KldA) * B(N x KldB)^T.
// CTA tile BM x BN, chunk BK, STG-stage cp.async ring, wait_group STG-2.
// Optional addm (mode-0 layout, stride Nld) added in the epilogue with bias.
// OUT_MODE 0: C[m*Nld+n]; OUT_MODE 1: m=b*TT+t -> C[(t*BB+b)*Nld+n]
// ---------------------------------------------------------------------------
template <int BM, int BN, int BK, int STG, int NC, int OUT_MODE>
__device__ void mma_gemm_dev(const float* __restrict__ A, const float* __restrict__ Bm,
                             const float* __restrict__ bias,
                             const float* __restrict__ addm, float* __restrict__ C,
                             int mbase, int n0, int Nld, int KldA, int KldB) {
    constexpr int WARPS_M = BM / 32;
    constexpr int WARPS_N = 8 / WARPS_M;
    constexpr int WN = BN / WARPS_N;
    constexpr int NB = WN / 8;
    constexpr int PAD = BK + 4;
    constexpr int CH = (BM + BN) * PAD;
    constexpr int SEG = BK / 4;
    constexpr int ROWS_PER_PASS = 1024 / BK;

    extern __shared__ __align__(16) uint32_t sm[];
    const uint32_t sm_sh = cvta_sh(sm);

    const int tid = threadIdx.x;
    const int wid = tid >> 5, lane = tid & 31;
    const int wm = wid % WARPS_M;
    const int wn = wid / WARPS_M;
    const int gid = lane >> 2;
    const int tig = lane & 3;

    const float* Ab = A + (size_t)mbase * KldA;
    const float* Bb = Bm + (size_t)n0 * KldB;

    float d[2][NB][4];
#pragma unroll
    for (int f = 0; f < 2; f++)
#pragma unroll
        for (int nb = 0; nb < NB; nb++)
#pragma unroll
            for (int c = 0; c < 4; c++) d[f][nb][c] = 0.0f;

    const int lr = tid / SEG;
    const int lj = tid % SEG;
    auto cp_chunk = [&](int st, int k0) {
        uint32_t abase = sm_sh + (uint32_t)st * CH * 4;
#pragma unroll
        for (int it = 0; it < BM / ROWS_PER_PASS; it++) {
            int r = lr + it * ROWS_PER_PASS;
            cp16(abase + (uint32_t)(r * PAD + lj * 4) * 4,
                 Ab + (size_t)r * KldA + k0 + lj * 4);
        }
        uint32_t bbase = abase + BM * PAD * 4;
#pragma unroll
        for (int it = 0; it < BN / ROWS_PER_PASS; it++) {
            int r = lr + it * ROWS_PER_PASS;
            cp16(bbase + (uint32_t)(r * PAD + lj * 4) * 4,
                 Bb + (size_t)r * KldB + k0 + lj * 4);
        }
    };

#pragma unroll
    for (int i = 0; i < STG - 1; i++) {
        if (i < NC) cp_chunk(i, i * BK);
        CP_COMMIT();
    }

    const int pa_off = (wm * 32 + gid) * PAD + tig;
    const int pb_off = (wn * WN + gid) * PAD + tig;

    int st = 0;
    for (int i = 0; i < NC; i++) {
        cp_wait<STG - 2>();
        __syncthreads();

        const uint32_t* sa = sm + st * CH + pa_off;
        const uint32_t* sb = sm + st * CH + BM * PAD + pb_off;

#pragma unroll
        for (int s = 0; s < BK / 8; s++) {
            const int ko = s * 8;
            uint32_t a[2][4];
#pragma unroll
            for (int f = 0; f < 2; f++) {
                const uint32_t* q = sa + f * (16 * PAD) + ko;
                a[f][0] = q[0];
                a[f][1] = q[8 * PAD];
                a[f][2] = q[4];
                a[f][3] = q[8 * PAD + 4];
            }
            uint32_t b[NB][2];
#pragma unroll
            for (int nb = 0; nb < NB; nb++) {
                const uint32_t* q = sb + nb * (8 * PAD) + ko;
                b[nb][0] = q[0];
                b[nb][1] = q[4];
            }
#pragma unroll
            for (int f = 0; f < 2; f++)
#pragma unroll
                for (int nb = 0; nb < NB; nb++)
                    mma_tf32(d[f][nb], a[f], b[nb]);
        }

        const int nx = i + STG - 1;
        if (nx < NC) {
            int stn = nx % STG;
            cp_chunk(stn, nx * BK);
        }
        CP_COMMIT();
        if (++st == STG) st = 0;
    }

    // ---- epilogue ----
#pragma unroll
    for (int f = 0; f < 2; f++) {
        int m0 = mbase + wm * 32 + f * 16 + gid;
        int m1 = m0 + 8;
        float* row0;
        float* row1;
        if (OUT_MODE == 0) {
            row0 = C + (size_t)m0 * Nld;
            row1 = C + (size_t)m1 * Nld;
        } else {
            row0 = C + (size_t)((m0 & 63) * BB + (m0 >> 6)) * Nld;
            row1 = C + (size_t)((m1 & 63) * BB + (m1 >> 6)) * Nld;
        }
#pragma unroll
        for (int nb = 0; nb < NB; nb++) {
            int cn = n0 + wn * WN + nb * 8 + 2 * tig;
            float2 bb = make_float2(0.f, 0.f);
            if (bias) bb = *(const float2*)(bias + cn);
            float2 a0 = make_float2(0.f, 0.f), a1 = make_float2(0.f, 0.f);
            if (addm) {
                a0 = *(const float2*)(addm + (size_t)m0 * Nld + cn);
                a1 = *(const float2*)(addm + (size_t)m1 * Nld + cn);
            }
            float2 o0 = make_float2(d[f][nb][0] + bb.x + a0.x, d[f][nb][1] + bb.y + a0.y);
            float2 o1 = make_float2(d[f][nb][2] + bb.x + a1.x, d[f][nb][3] + bb.y + a1.y);
            *(float2*)(row0 + cn) = o0;
            *(float2*)(row1 + cn) = o1;
        }
    }
}

// Fused independent GEMMs: grid.y 0..7 wq | 8..39 uh | 40..47 s2=src@Ws^T
__global__ __launch_bounds__(256, 2)
void gqc_mma(const float* __restrict__ rsrc, const float* __restrict__ rmem,
             const float* __restrict__ rWq, const float* __restrict__ bq,
             const float* __restrict__ rWc, const float* __restrict__ rWout,
             float* __restrict__ wq, float* __restrict__ uh,
             float* __restrict__ s2) {
    int my = blockIdx.y;
    if (my < 8)
        mma_gemm_dev<128, 64, 32, 4, 16, 0>(rsrc, rWq, bq, nullptr, wq,
                                            my * 128, blockIdx.x * 64, DD, DD, DD);
    else if (my < 40)
        mma_gemm_dev<128, 64, 32, 4, 16, 0>(rmem, rWc, nullptr, nullptr, uh,
                                            (my - 8) * 128, blockIdx.x * 64, DD, DD, DD);
    else
        mma_gemm_dev<128, 64, 32, 4, 16, 0>(rsrc, rWout + DD, nullptr, nullptr, s2,
                                            (my - 40) * 128, blockIdx.x * 64, DD, DD, 2 * DD);
}

// Output GEMM (c part only, K=512): c @ Wc_out^T + s2 + bias -> (T,B,D)
__global__ __launch_bounds__(256, 2)
void gout_mma(const float* __restrict__ cc, const float* __restrict__ rWout,
              const float* __restrict__ bout, const float* __restrict__ s2,
              float* __restrict__ out) {
    mma_gemm_dev<64, 64, 64, 3, 8, 1>(cc, rWout, bout, s2, out,
                                      blockIdx.y * 64, blockIdx.x * 64, DD, DD, 2 * DD);
}

// ---------------------------------------------------------------------------
// Align + sparsemax + context: 8 t's per block, 512 threads (16 warps),
// 128 CTAs. uh L2 traffic halves vs 4-t blocking while chip-resident warp
// count stays 2048 (R12's regression was warp count, not blocking).
// Score loop: float4 LDG/LDS, 8 tanh per loaded u. Michelot: warp-per-row,
// pure shuffles, no barriers.
// ---------------------------------------------------------------------------
__global__ __launch_bounds__(512)
void align8_kernel(const float* __restrict__ wq, const float* __restrict__ uh,
                   const float* __restrict__ mem, const int* __restrict__ mask,
                   const float* __restrict__ v,
                   float* __restrict__ out_align, float* __restrict__ cc) {
    __shared__ float s_wq[8][DD];   // 16 KB
    __shared__ float s_v[DD];       // 2 KB
    __shared__ float s_z[8][SS];    // 8 KB
    __shared__ float s_p[8][SS];    // 8 KB
    __shared__ int s_mk[SS];        // 1 KB

    const int tid = threadIdx.x;
    const int b  = blockIdx.x >> 3;        // 8 blocks per b
    const int t0 = (blockIdx.x & 7) * 8;

    for (int i = tid; i < 8 * DD; i += 512) {
        int tt = i >> 9, d = i & 511;
        s_wq[tt][d] = wq[((size_t)(b * TT + t0 + tt)) * DD + d];
    }
    s_v[tid & 511] = v[tid & 511];
    if (tid < SS) s_mk[tid] = mask[b * SS + tid];
    __syncthreads();

    const int warp = tid >> 5, lane = tid & 31;

    // ---- score loop: 16 warps stride the 256 s-rows ----
    for (int s = warp; s < SS; s += 16) {
        if (!s_mk[s]) {
            if (lane == 0) {
#pragma unroll
                for (int tt = 0; tt < 8; tt++) s_z[tt][s] = -1e9f;
            }
            continue;
        }
        const float4* uhr = (const float4*)(uh + ((size_t)(b * SS + s)) * DD);
        float acc[8];
#pragma unroll
        for (int tt = 0; tt < 8; tt++) acc[tt] = 0.0f;
#pragma unroll
        for (int i = 0; i < 4; i++) {
            int d4 = lane + 32 * i;             // float4 index 0..127
            float4 u = uhr[d4];
            float4 vv = *(const float4*)&s_v[d4 * 4];
#pragma unroll
            for (int tt = 0; tt < 8; tt++) {
                float4 w = *(const float4*)&s_wq[tt][d4 * 4];
                acc[tt] += vv.x * htanh(w.x + u.x) + vv.y * htanh(w.y + u.y)
                         + vv.z * htanh(w.z + u.z) + vv.w * htanh(w.w + u.w);
            }
        }
#pragma unroll
        for (int tt = 0; tt < 8; tt++) {
#pragma unroll
            for (int off = 16; off; off >>= 1)
                acc[tt] += __shfl_xor_sync(0xffffffffu, acc[tt], off);
        }
        if (lane == 0) {
#pragma unroll
            for (int tt = 0; tt < 8; tt++) s_z[tt][s] = acc[tt];
        }
    }
    __syncthreads();

    // ---- sparsemax via Michelot: warp w (< 8) owns row t0+w ----
    if (warp < 8) {
        const int tt = warp;
        float z[8];
        bool act[8];
#pragma unroll
        for (int j = 0; j < 8; j++) {
            z[j] = s_z[tt][lane + 32 * j];
            act[j] = true;
        }
        float tau = 0.0f;
        int prev = -1;
        for (int it = 0; it < 300; it++) {
            float sv = 0.f, cv = 0.f;
#pragma unroll
            for (int j = 0; j < 8; j++)
                if (act[j]) { sv += z[j]; cv += 1.0f; }
#pragma unroll
            for (int off = 16; off; off >>= 1) {
                sv += __shfl_xor_sync(0xffffffffu, sv, off);
                cv += __shfl_xor_sync(0xffffffffu, cv, off);
            }
            int c = (int)cv;
            if (c == prev) break;
            tau = (sv - 1.0f) / cv;
            prev = c;
#pragma unroll
            for (int j = 0; j < 8; j++) act[j] = z[j] > tau;
        }
        float* oa = out_align + ((size_t)(t0 + tt) * BB + b) * SS;
#pragma unroll
        for (int j = 0; j < 8; j++) {
            float p = fmaxf(z[j] - tau, 0.0f);
            s_p[tt][lane + 32 * j] = p;
            oa[lane + 32 * j] = p;
        }
    }
    __syncthreads();

    // ---- context vectors: one d element per thread, 8 t accumulators ----
    const int d = tid;                      // 0..511
    const float* memb = mem + (size_t)b * SS * DD;
    float c[8];
#pragma unroll
    for (int tt = 0; tt < 8; tt++) c[tt] = 0.f;
    for (int s = 0; s < SS; s++) {
        float p[8];
        float psum = 0.f;
#pragma unroll
        for (int tt = 0; tt < 8; tt++) { p[tt] = s_p[tt][s]; psum += p[tt]; }
        if (psum != 0.0f) {
            float r = memb[(size_t)s * DD + d];
#pragma unroll
            for (int tt = 0; tt < 8; tt++) c[tt] = fmaf(p[tt], r, c[tt]);
        }
    }
#pragma unroll
    for (int tt = 0; tt < 8; tt++) {
        cc[(size_t)(b * TT + t0 + tt) * DD + d] = __uint_as_float(to_tf32(c[tt]));
    }
}

// ---------------------------------------------------------------------------
extern "C" void kernel_launch(void* const* d_in, const int* in_sizes, int n_in,
                              void* d_out, int out_size) {
    const float* source      = (const float*)d_in[0];
    const float* memory_bank = (const float*)d_in[1];
    const int*   memory_mask = (const int*)d_in[2];
    const float* W_q         = (const float*)d_in[3];
    const float* b_q         = (const float*)d_in[4];
    const float* W_c         = (const float*)d_in[5];
    const float* v           = (const float*)d_in[6];
    const float* W_out       = (const float*)d_in[7];
    const float* b_out       = (const float*)d_in[8];

    float* out       = (float*)d_out;
    float* out_attn  = out;                         // (T,B,D)
    float* out_align = out + (size_t)TT * BB * DD;  // (T,B,S)

    float *p_wq, *p_uh, *p_cc, *p_s2, *p_rsrc, *p_rmem, *p_rwq, *p_rwc, *p_rwout;
    cudaGetSymbolAddress((void**)&p_wq, g_wq);
    cudaGetSymbolAddress((void**)&p_uh, g_uh);
    cudaGetSymbolAddress((void**)&p_cc, g_cc);
    cudaGetSymbolAddress((void**)&p_s2, g_s2);
    cudaGetSymbolAddress((void**)&p_rsrc, g_rsrc);
    cudaGetSymbolAddress((void**)&p_rmem, g_rmem);
    cudaGetSymbolAddress((void**)&p_rwq, g_rwq);
    cudaGetSymbolAddress((void**)&p_rwc, g_rwc);
    cudaGetSymbolAddress((void**)&p_rwout, g_rwout);

    const int smem_qc  = 4 * (128 + 64) * 36 * 4;  // 110592
    const int smem_out = 3 * (64 + 64) * 68 * 4;   // 104448
    cudaFuncSetAttribute(gqc_mma, cudaFuncAttributeMaxDynamicSharedMemorySize, smem_qc);
    cudaFuncSetAttribute(gout_mma, cudaFuncAttributeMaxDynamicSharedMemorySize, smem_out);

    // 0) pre-round all GEMM inputs (exact 1D grid: 917504 float4 / 256)
    round_kernel<<<3584, 256>>>(source, memory_bank, W_q, W_c, W_out,
                                p_rsrc, p_rmem, p_rwq, p_rwc, p_rwout);

    // 1) wq, uh, s2 (tf32 mma.sync + cp.async): 384 CTAs
    gqc_mma<<<dim3(8, 48), 256, smem_qc>>>(
        p_rsrc, p_rmem, p_rwq, b_q, p_rwc, p_rwout, p_wq, p_uh, p_s2);

    // 2) align + sparsemax + context: 128 CTAs x 512 threads (8 t's each)
    align8_kernel<<<BB * (TT / 8), 512>>>(
        p_wq, p_uh, memory_bank, memory_mask, v, out_align, p_cc);

    // 3) attn_h = c @ Wc^T + s2 + bias -> (T,B,D): 128 CTAs, K=512
    gout_mma<<<dim3(8, 16), 256, smem_out>>>(p_cc, p_rwout, b_out, p_s2, out_attn);
}

// round 16
// speedup vs baseline: 1.2302x; 1.2302x over previous
#include <cuda_runtime.h>
#include <cuda_fp16.h>
#include <cstdint>

// Problem constants
#define BB 16
#define TT 64
#define SS 256
#define DD 512

// Scratch (device globals — no allocations allowed)
__device__ float  g_wq[BB * TT * DD];          // (B,T,D) fp32  2 MB
__device__ float  g_uh[BB * SS * DD];          // (B,S,D) fp32  8 MB
__device__ __half g_cc[BB * TT * DD];          // context, fp16 1 MB
__device__ float  g_s2[BB * TT * DD];          // src @ Ws^T    2 MB
// fp16 copies of GEMM inputs
__device__ __half g_rsrc[BB * TT * DD];        // 1 MB
__device__ __half g_rmem[BB * SS * DD];        // 4 MB
__device__ __half g_rwq[DD * DD];              // 0.5 MB
__device__ __half g_rwc[DD * DD];              // 0.5 MB
__device__ __half g_rwout[DD * 2 * DD];        // 1 MB

__device__ __forceinline__ float htanh(float x) {
    float y;
    asm("tanh.approx.f32 %0, %1;" : "=f"(y) : "f"(x));
    return y;
}
__device__ __forceinline__ void mma_f16(float* d, const uint32_t* a, const uint32_t* b) {
    asm volatile(
        "mma.sync.aligned.m16n8k16.row.col.f32.f16.f16.f32 "
        "{%0,%1,%2,%3}, {%4,%5,%6,%7}, {%8,%9}, {%0,%1,%2,%3};"
        : "+f"(d[0]), "+f"(d[1]), "+f"(d[2]), "+f"(d[3])
        : "r"(a[0]), "r"(a[1]), "r"(a[2]), "r"(a[3]), "r"(b[0]), "r"(b[1]));
}
__device__ __forceinline__ uint32_t cvta_sh(const void* p) {
    uint32_t a;
    asm("{ .reg .u64 t; cvta.to.shared.u64 t, %1; cvt.u32.u64 %0, t; }"
        : "=r"(a) : "l"(p));
    return a;
}
__device__ __forceinline__ void cp16(uint32_t dst, const void* src) {
    asm volatile("cp.async.cg.shared.global [%0], [%1], 16;"
                 :: "r"(dst), "l"(src) : "memory");
}
#define CP_COMMIT() asm volatile("cp.async.commit_group;" ::: "memory")
#define CP_WAIT2()  asm volatile("cp.async.wait_group 2;" ::: "memory")
#define BAR64(id)   asm volatile("bar.sync %0, 64;" :: "r"(id) : "memory")

// ---------------------------------------------------------------------------
// Pre-round pass: fp32 -> fp16 for all GEMM inputs. Flat 1D grid (3584 x 256).
// float4 boundaries: src 131072 | mem 524288 | wq 65536 | wc 65536 | wout 131072
// ---------------------------------------------------------------------------
__global__ __launch_bounds__(256)
void round_kernel(const float* __restrict__ src, const float* __restrict__ mem,
                  const float* __restrict__ Wq, const float* __restrict__ Wc,
                  const float* __restrict__ Wout,
                  __half* __restrict__ rsrc, __half* __restrict__ rmem,
                  __half* __restrict__ rwq, __half* __restrict__ rwc,
                  __half* __restrict__ rwout) {
    int i = blockIdx.x * 256 + threadIdx.x;
    const float* in;
    __half* outp;
    int off;
    if (i < 131072)      { in = src;  outp = rsrc;  off = 0; }
    else if (i < 655360) { in = mem;  outp = rmem;  off = 131072; }
    else if (i < 720896) { in = Wq;   outp = rwq;   off = 655360; }
    else if (i < 786432) { in = Wc;   outp = rwc;   off = 720896; }
    else                 { in = Wout; outp = rwout; off = 786432; }
    int j = i - off;
    float4 v = *(const float4*)(in + (size_t)j * 4);
    __half2 h0 = __floats2half2_rn(v.x, v.y);
    __half2 h1 = __floats2half2_rn(v.z, v.w);
    uint2 o2;
    o2.x = *(uint32_t*)&h0;
    o2.y = *(uint32_t*)&h1;
    *(uint2*)(outp + (size_t)j * 4) = o2;
}

// ---------------------------------------------------------------------------
// fp16 mma.sync (m16n8k16) GEMM: C = A(M x KldA) * B(N x KldB)^T, fp32 accum.
// Units: K measured in halfs; chunk = 64 halfs (128B/row), 4 k16-steps/chunk.
// smem rows: 32 half2 data + 4 half2 pad (PAD=36 words) — conflict-free frags
// (same addressing as the proven tf32 path, elements = half2).
// 4-stage cp.async ring, wait_group 2, one __syncthreads per chunk.
// Optional addm (fp32, mode-0 layout, stride Nld) added in epilogue w/ bias.
// OUT_MODE 0: C[m*Nld+n]; OUT_MODE 1: m=b*TT+t -> C[(t*BB+b)*Nld+n]
// ---------------------------------------------------------------------------
template <int BM, int BN, int NC, int OUT_MODE>
__device__ void mma_gemm_dev(const __half* __restrict__ A, const __half* __restrict__ Bm,
                             const float* __restrict__ bias,
                             const float* __restrict__ addm, float* __restrict__ C,
                             int mbase, int n0, int Nld, int KldA, int KldB) {
    constexpr int WARPS_M = BM / 32;
    constexpr int WARPS_N = 8 / WARPS_M;
    constexpr int WN = BN / WARPS_N;
    constexpr int NB = WN / 8;
    constexpr int BKH = 64;               // halfs per chunk
    constexpr int PAD = 36;               // half2 words per row (32 data + 4)
    constexpr int CH = (BM + BN) * PAD;   // uint32 per stage
    constexpr int STG = 4;
    constexpr int SEG = 8;                // 16B segments per row (64 halfs)

    extern __shared__ __align__(16) uint32_t sm[];
    const uint32_t sm_sh = cvta_sh(sm);

    const int tid = threadIdx.x;
    const int wid = tid >> 5, lane = tid & 31;
    const int wm = wid % WARPS_M;
    const int wn = wid / WARPS_M;
    const int gid = lane >> 2;
    const int tig = lane & 3;

    const __half* Ab = A + (size_t)mbase * KldA;
    const __half* Bb = Bm + (size_t)n0 * KldB;

    float d[2][NB][4];
#pragma unroll
    for (int f = 0; f < 2; f++)
#pragma unroll
        for (int nb = 0; nb < NB; nb++)
#pragma unroll
            for (int c = 0; c < 4; c++) d[f][nb][c] = 0.0f;

    const int lr = tid >> 3;              // loader row (32 per pass)
    const int lj = tid & 7;               // loader 16B segment
    auto cp_chunk = [&](int st, int k0) {
        uint32_t abase = sm_sh + (uint32_t)st * CH * 4;
#pragma unroll
        for (int it = 0; it < BM / 32; it++) {
            int r = lr + it * 32;
            cp16(abase + (uint32_t)(r * PAD + lj * 4) * 4,
                 Ab + (size_t)r * KldA + k0 + lj * 8);
        }
        uint32_t bbase = abase + BM * PAD * 4;
#pragma unroll
        for (int it = 0; it < BN / 32; it++) {
            int r = lr + it * 32;
            cp16(bbase + (uint32_t)(r * PAD + lj * 4) * 4,
                 Bb + (size_t)r * KldB + k0 + lj * 8);
        }
    };

#pragma unroll
    for (int i = 0; i < STG - 1; i++) {
        if (i < NC) cp_chunk(i, i * BKH);
        CP_COMMIT();
    }

    const int pa_off = (wm * 32 + gid) * PAD + tig;
    const int pb_off = (wn * WN + gid) * PAD + tig;

    int st = 0;
    for (int i = 0; i < NC; i++) {
        CP_WAIT2();
        __syncthreads();

        const uint32_t* sa = sm + st * CH + pa_off;
        const uint32_t* sb = sm + st * CH + BM * PAD + pb_off;

#pragma unroll
        for (int s = 0; s < 4; s++) {       // 4 k16-steps per 64-half chunk
            const int ko = s * 8;           // 8 half2 per k16 step
            uint32_t a[2][4];
#pragma unroll
            for (int f = 0; f < 2; f++) {
                const uint32_t* q = sa + f * (16 * PAD) + ko;
                a[f][0] = q[0];
                a[f][1] = q[8 * PAD];
                a[f][2] = q[4];
                a[f][3] = q[8 * PAD + 4];
            }
            uint32_t b[NB][2];
#pragma unroll
            for (int nb = 0; nb < NB; nb++) {
                const uint32_t* q = sb + nb * (8 * PAD) + ko;
                b[nb][0] = q[0];
                b[nb][1] = q[4];
            }
#pragma unroll
            for (int f = 0; f < 2; f++)
#pragma unroll
                for (int nb = 0; nb < NB; nb++)
                    mma_f16(d[f][nb], a[f], b[nb]);
        }

        const int nx = i + STG - 1;
        if (nx < NC) cp_chunk(nx % STG, nx * BKH);
        CP_COMMIT();
        if (++st == STG) st = 0;
    }

    // ---- epilogue (fp32) ----
#pragma unroll
    for (int f = 0; f < 2; f++) {
        int m0 = mbase + wm * 32 + f * 16 + gid;
        int m1 = m0 + 8;
        float* row0;
        float* row1;
        if (OUT_MODE == 0) {
            row0 = C + (size_t)m0 * Nld;
            row1 = C + (size_t)m1 * Nld;
        } else {
            row0 = C + (size_t)((m0 & 63) * BB + (m0 >> 6)) * Nld;
            row1 = C + (size_t)((m1 & 63) * BB + (m1 >> 6)) * Nld;
        }
#pragma unroll
        for (int nb = 0; nb < NB; nb++) {
            int cn = n0 + wn * WN + nb * 8 + 2 * tig;
            float2 bb = make_float2(0.f, 0.f);
            if (bias) bb = *(const float2*)(bias + cn);
            float2 a0 = make_float2(0.f, 0.f), a1 = make_float2(0.f, 0.f);
            if (addm) {
                a0 = *(const float2*)(addm + (size_t)m0 * Nld + cn);
                a1 = *(const float2*)(addm + (size_t)m1 * Nld + cn);
            }
            float2 o0 = make_float2(d[f][nb][0] + bb.x + a0.x, d[f][nb][1] + bb.y + a0.y);
            float2 o1 = make_float2(d[f][nb][2] + bb.x + a1.x, d[f][nb][3] + bb.y + a1.y);
            *(float2*)(row0 + cn) = o0;
            *(float2*)(row1 + cn) = o1;
        }
    }
}

// Fused independent GEMMs: grid.y 0..7 wq | 8..39 uh | 40..47 s2=src@Ws^T
__global__ __launch_bounds__(256, 2)
void gqc_mma(const __half* __restrict__ rsrc, const __half* __restrict__ rmem,
             const __half* __restrict__ rWq, const float* __restrict__ bq,
             const __half* __restrict__ rWc, const __half* __restrict__ rWout,
             float* __restrict__ wq, float* __restrict__ uh,
             float* __restrict__ s2) {
    int my = blockIdx.y;
    if (my < 8)
        mma_gemm_dev<128, 64, 8, 0>(rsrc, rWq, bq, nullptr, wq,
                                    my * 128, blockIdx.x * 64, DD, DD, DD);
    else if (my < 40)
        mma_gemm_dev<128, 64, 8, 0>(rmem, rWc, nullptr, nullptr, uh,
                                    (my - 8) * 128, blockIdx.x * 64, DD, DD, DD);
    else
        mma_gemm_dev<128, 64, 8, 0>(rsrc, rWout + DD, nullptr, nullptr, s2,
                                    (my - 40) * 128, blockIdx.x * 64, DD, DD, 2 * DD);
}

// Output GEMM (c part, K=512): c(fp16) @ Wc_out^T + s2 + bias -> (T,B,D)
__global__ __launch_bounds__(256, 2)
void gout_mma(const __half* __restrict__ cc, const __half* __restrict__ rWout,
              const float* __restrict__ bout, const float* __restrict__ s2,
              float* __restrict__ out) {
    mma_gemm_dev<64, 64, 8, 1>(cc, rWout, bout, s2, out,
                               blockIdx.y * 64, blockIdx.x * 64, DD, DD, 2 * DD);
}

// ---------------------------------------------------------------------------
// Align + sparsemax (Michelot, 4 rows via named barriers) + context.
// R13 config: 4 t's per block, 256 CTAs, float4 score loop. cc written fp16.
// ---------------------------------------------------------------------------
__global__ __launch_bounds__(256)
void align4_kernel(const float* __restrict__ wq, const float* __restrict__ uh,
                   const float* __restrict__ mem, const int* __restrict__ mask,
                   const float* __restrict__ v,
                   float* __restrict__ out_align, __half* __restrict__ cc) {
    __shared__ float s_wq[4][DD];
    __shared__ float s_v[DD];
    __shared__ float s_z[4][SS];
    __shared__ float s_p[4][SS];
    __shared__ int s_mk[SS];
    __shared__ float s_red[4][2][2];

    const int tid = threadIdx.x;
    const int b  = blockIdx.x >> 4;
    const int t0 = (blockIdx.x & 15) * 4;

    for (int i = tid; i < 4 * DD; i += 256) {
        int tt = i >> 9, d = i & 511;
        s_wq[tt][d] = wq[((size_t)(b * TT + t0 + tt)) * DD + d];
    }
    s_v[tid] = v[tid];
    s_v[tid + 256] = v[tid + 256];
    s_mk[tid] = mask[b * SS + tid];
    __syncthreads();

    const int warp = tid >> 5, lane = tid & 31;
    for (int s = warp; s < SS; s += 8) {
        if (!s_mk[s]) {
            if (lane == 0) {
                s_z[0][s] = -1e9f; s_z[1][s] = -1e9f;
                s_z[2][s] = -1e9f; s_z[3][s] = -1e9f;
            }
            continue;
        }
        const float4* uhr = (const float4*)(uh + ((size_t)(b * SS + s)) * DD);
        float a0 = 0.f, a1 = 0.f, a2 = 0.f, a3 = 0.f;
#pragma unroll
        for (int i = 0; i < 4; i++) {
            int d4 = lane + 32 * i;
            float4 u = uhr[d4];
            float4 vv = *(const float4*)&s_v[d4 * 4];
            float4 w0 = *(const float4*)&s_wq[0][d4 * 4];
            float4 w1 = *(const float4*)&s_wq[1][d4 * 4];
            float4 w2 = *(const float4*)&s_wq[2][d4 * 4];
            float4 w3 = *(const float4*)&s_wq[3][d4 * 4];
            a0 += vv.x * htanh(w0.x + u.x) + vv.y * htanh(w0.y + u.y)
                + vv.z * htanh(w0.z + u.z) + vv.w * htanh(w0.w + u.w);
            a1 += vv.x * htanh(w1.x + u.x) + vv.y * htanh(w1.y + u.y)
                + vv.z * htanh(w1.z + u.z) + vv.w * htanh(w1.w + u.w);
            a2 += vv.x * htanh(w2.x + u.x) + vv.y * htanh(w2.y + u.y)
                + vv.z * htanh(w2.z + u.z) + vv.w * htanh(w2.w + u.w);
            a3 += vv.x * htanh(w3.x + u.x) + vv.y * htanh(w3.y + u.y)
                + vv.z * htanh(w3.z + u.z) + vv.w * htanh(w3.w + u.w);
        }
#pragma unroll
        for (int off = 16; off; off >>= 1) {
            a0 += __shfl_xor_sync(0xffffffffu, a0, off);
            a1 += __shfl_xor_sync(0xffffffffu, a1, off);
            a2 += __shfl_xor_sync(0xffffffffu, a2, off);
            a3 += __shfl_xor_sync(0xffffffffu, a3, off);
        }
        if (lane == 0) {
            s_z[0][s] = a0; s_z[1][s] = a1; s_z[2][s] = a2; s_z[3][s] = a3;
        }
    }
    __syncthreads();

    // ---- sparsemax via Michelot, 4 rows concurrently (64 threads/row) ----
    {
        const int tt = tid >> 6;
        const int u  = tid & 63;
        const int lw = (tid >> 5) & 1;
        float z[4];
        bool act[4];
#pragma unroll
        for (int j = 0; j < 4; j++) {
            z[j] = s_z[tt][u + 64 * j];
            act[j] = true;
        }
        float tau = 0.0f;
        int prev = -1;
        for (int it = 0; it < 260; it++) {
            float sv = 0.f, cv = 0.f;
#pragma unroll
            for (int j = 0; j < 4; j++)
                if (act[j]) { sv += z[j]; cv += 1.0f; }
#pragma unroll
            for (int off = 16; off; off >>= 1) {
                sv += __shfl_xor_sync(0xffffffffu, sv, off);
                cv += __shfl_xor_sync(0xffffffffu, cv, off);
            }
            if (lane == 0) { s_red[tt][lw][0] = sv; s_red[tt][lw][1] = cv; }
            BAR64(1 + tt);
            float ts = s_red[tt][0][0] + s_red[tt][1][0];
            float tc = s_red[tt][0][1] + s_red[tt][1][1];
            BAR64(1 + tt);
            int c = (int)tc;
            if (c == prev) break;
            tau = (ts - 1.0f) / tc;
            prev = c;
#pragma unroll
            for (int j = 0; j < 4; j++) act[j] = z[j] > tau;
        }
#pragma unroll
        for (int j = 0; j < 4; j++) {
            float p = fmaxf(z[j] - tau, 0.0f);
            s_p[tt][u + 64 * j] = p;
            out_align[((size_t)(t0 + tt) * BB + b) * SS + u + 64 * j] = p;
        }
    }
    __syncthreads();

    // ---- context vectors (raw fp32 mem; results written fp16 into cc) ----
    const int d0 = tid, d1 = tid + 256;
    const float* memb = mem + (size_t)b * SS * DD;
    float c00 = 0.f, c01 = 0.f, c10 = 0.f, c11 = 0.f;
    float c20 = 0.f, c21 = 0.f, c30 = 0.f, c31 = 0.f;
    for (int s = 0; s < SS; s++) {
        float p0 = s_p[0][s], p1 = s_p[1][s], p2 = s_p[2][s], p3 = s_p[3][s];
        if (p0 + p1 + p2 + p3 != 0.0f) {
            const float* row = memb + (size_t)s * DD;
            float r0 = row[d0], r1 = row[d1];
            c00 = fmaf(p0, r0, c00); c01 = fmaf(p0, r1, c01);
            c10 = fmaf(p1, r0, c10); c11 = fmaf(p1, r1, c11);
            c20 = fmaf(p2, r0, c20); c21 = fmaf(p2, r1, c21);
            c30 = fmaf(p3, r0, c30); c31 = fmaf(p3, r1, c31);
        }
    }
    float cc0[4] = {c00, c10, c20, c30};
    float cc1[4] = {c01, c11, c21, c31};
#pragma unroll
    for (int tt = 0; tt < 4; tt++) {
        __half* crow = cc + (size_t)(b * TT + t0 + tt) * DD;
        crow[d0] = __float2half_rn(cc0[tt]);
        crow[d1] = __float2half_rn(cc1[tt]);
    }
}

// ---------------------------------------------------------------------------
extern "C" void kernel_launch(void* const* d_in, const int* in_sizes, int n_in,
                              void* d_out, int out_size) {
    const float* source      = (const float*)d_in[0];
    const float* memory_bank = (const float*)d_in[1];
    const int*   memory_mask = (const int*)d_in[2];
    const float* W_q         = (const float*)d_in[3];
    const float* b_q         = (const float*)d_in[4];
    const float* W_c         = (const float*)d_in[5];
    const float* v           = (const float*)d_in[6];
    const float* W_out       = (const float*)d_in[7];
    const float* b_out       = (const float*)d_in[8];

    float* out       = (float*)d_out;
    float* out_attn  = out;                         // (T,B,D)
    float* out_align = out + (size_t)TT * BB * DD;  // (T,B,S)

    float *p_wq, *p_uh, *p_s2;
    __half *p_cc, *p_rsrc, *p_rmem, *p_rwq, *p_rwc, *p_rwout;
    cudaGetSymbolAddress((void**)&p_wq, g_wq);
    cudaGetSymbolAddress((void**)&p_uh, g_uh);
    cudaGetSymbolAddress((void**)&p_cc, g_cc);
    cudaGetSymbolAddress((void**)&p_s2, g_s2);
    cudaGetSymbolAddress((void**)&p_rsrc, g_rsrc);
    cudaGetSymbolAddress((void**)&p_rmem, g_rmem);
    cudaGetSymbolAddress((void**)&p_rwq, g_rwq);
    cudaGetSymbolAddress((void**)&p_rwc, g_rwc);
    cudaGetSymbolAddress((void**)&p_rwout, g_rwout);

    const int smem_qc  = 4 * (128 + 64) * 36 * 4;  // 110592
    const int smem_out = 4 * (64 + 64) * 36 * 4;   // 73728
    cudaFuncSetAttribute(gqc_mma, cudaFuncAttributeMaxDynamicSharedMemorySize, smem_qc);
    cudaFuncSetAttribute(gout_mma, cudaFuncAttributeMaxDynamicSharedMemorySize, smem_out);

    // 0) fp32 -> fp16 conversion of all GEMM inputs
    round_kernel<<<3584, 256>>>(source, memory_bank, W_q, W_c, W_out,
                                p_rsrc, p_rmem, p_rwq, p_rwc, p_rwout);

    // 1) wq, uh, s2 (fp16 mma.sync k16 + cp.async): 384 CTAs
    gqc_mma<<<dim3(8, 48), 256, smem_qc>>>(
        p_rsrc, p_rmem, p_rwq, b_q, p_rwc, p_rwout, p_wq, p_uh, p_s2);

    // 2) align + sparsemax + context: 256 CTAs (4 t's each)
    align4_kernel<<<BB * (TT / 4), 256>>>(
        p_wq, p_uh, memory_bank, memory_mask, v, out_align, p_cc);

    // 3) attn_h = c @ Wc^T + s2 + bias -> (T,B,D): 128 CTAs, K=512
    gout_mma<<<dim3(8, 16), 256, smem_out>>>(p_cc, p_rwout, b_out, p_s2, out_attn);
}

// round 17
// speedup vs baseline: 1.3815x; 1.1230x over previous
#include <cuda_runtime.h>
#include <cuda_fp16.h>
#include <cstdint>

// Problem constants
#define BB 16
#define TT 64
#define SS 256
#define DD 512

// Scratch (device globals — no allocations allowed)
__device__ float  g_wq[BB * TT * DD];          // (B,T,D) fp32  2 MB
__device__ float  g_uh[BB * SS * DD];          // (B,S,D) fp32  8 MB
__device__ __half g_cc[BB * TT * DD];          // context, fp16 1 MB
__device__ float  g_s2[BB * TT * DD];          // src @ Ws^T    2 MB
// fp16 copies of GEMM inputs
__device__ __half g_rsrc[BB * TT * DD];        // 1 MB
__device__ __half g_rmem[BB * SS * DD];        // 4 MB
__device__ __half g_rwq[DD * DD];              // 0.5 MB
__device__ __half g_rwc[DD * DD];              // 0.5 MB
__device__ __half g_rwout[DD * 2 * DD];        // 1 MB

__device__ __forceinline__ float htanh(float x) {
    float y;
    asm("tanh.approx.f32 %0, %1;" : "=f"(y) : "f"(x));
    return y;
}
__device__ __forceinline__ void mma_f16(float* d, const uint32_t* a, const uint32_t* b) {
    asm volatile(
        "mma.sync.aligned.m16n8k16.row.col.f32.f16.f16.f32 "
        "{%0,%1,%2,%3}, {%4,%5,%6,%7}, {%8,%9}, {%0,%1,%2,%3};"
        : "+f"(d[0]), "+f"(d[1]), "+f"(d[2]), "+f"(d[3])
        : "r"(a[0]), "r"(a[1]), "r"(a[2]), "r"(a[3]), "r"(b[0]), "r"(b[1]));
}
__device__ __forceinline__ uint32_t cvta_sh(const void* p) {
    uint32_t a;
    asm("{ .reg .u64 t; cvta.to.shared.u64 t, %1; cvt.u32.u64 %0, t; }"
        : "=r"(a) : "l"(p));
    return a;
}
__device__ __forceinline__ void cp16(uint32_t dst, const void* src) {
    asm volatile("cp.async.cg.shared.global [%0], [%1], 16;"
                 :: "r"(dst), "l"(src) : "memory");
}
#define CP_COMMIT() asm volatile("cp.async.commit_group;" ::: "memory")
#define CP_WAIT2()  asm volatile("cp.async.wait_group 2;" ::: "memory")
#define BAR64(id)   asm volatile("bar.sync %0, 64;" :: "r"(id) : "memory")

// ---------------------------------------------------------------------------
// Pre-round pass: fp32 -> fp16 for all GEMM inputs. Flat 1D grid (3584 x 256).
// float4 boundaries: src 131072 | mem 524288 | wq 65536 | wc 65536 | wout 131072
// ---------------------------------------------------------------------------
__global__ __launch_bounds__(256)
void round_kernel(const float* __restrict__ src, const float* __restrict__ mem,
                  const float* __restrict__ Wq, const float* __restrict__ Wc,
                  const float* __restrict__ Wout,
                  __half* __restrict__ rsrc, __half* __restrict__ rmem,
                  __half* __restrict__ rwq, __half* __restrict__ rwc,
                  __half* __restrict__ rwout) {
    int i = blockIdx.x * 256 + threadIdx.x;
    const float* in;
    __half* outp;
    int off;
    if (i < 131072)      { in = src;  outp = rsrc;  off = 0; }
    else if (i < 655360) { in = mem;  outp = rmem;  off = 131072; }
    else if (i < 720896) { in = Wq;   outp = rwq;   off = 655360; }
    else if (i < 786432) { in = Wc;   outp = rwc;   off = 720896; }
    else                 { in = Wout; outp = rwout; off = 786432; }
    int j = i - off;
    float4 v = *(const float4*)(in + (size_t)j * 4);
    __half2 h0 = __floats2half2_rn(v.x, v.y);
    __half2 h1 = __floats2half2_rn(v.z, v.w);
    uint2 o2;
    o2.x = *(uint32_t*)&h0;
    o2.y = *(uint32_t*)&h1;
    *(uint2*)(outp + (size_t)j * 4) = o2;
}

// ---------------------------------------------------------------------------
// fp16 mma.sync (m16n8k16) GEMM: C = A(M x KldA) * B(N x KldB)^T, fp32 accum.
// chunk = 64 halfs (128B/row), 4 k16-steps per chunk, PAD=36 half2 words.
// 4-stage cp.async ring, wait_group 2, one __syncthreads per chunk.
// Optional addm (fp32, mode-0 layout, stride Nld) added in epilogue w/ bias.
// OUT_MODE 0: C[m*Nld+n]; OUT_MODE 1: m=b*TT+t -> C[(t*BB+b)*Nld+n]
// ---------------------------------------------------------------------------
template <int BM, int BN, int NC, int OUT_MODE>
__device__ void mma_gemm_dev(const __half* __restrict__ A, const __half* __restrict__ Bm,
                             const float* __restrict__ bias,
                             const float* __restrict__ addm, float* __restrict__ C,
                             int mbase, int n0, int Nld, int KldA, int KldB) {
    constexpr int WARPS_M = BM / 32;
    constexpr int WARPS_N = 8 / WARPS_M;
    constexpr int WN = BN / WARPS_N;
    constexpr int NB = WN / 8;
    constexpr int BKH = 64;
    constexpr int PAD = 36;
    constexpr int CH = (BM + BN) * PAD;
    constexpr int STG = 4;

    extern __shared__ __align__(16) uint32_t sm[];
    const uint32_t sm_sh = cvta_sh(sm);

    const int tid = threadIdx.x;
    const int wid = tid >> 5, lane = tid & 31;
    const int wm = wid % WARPS_M;
    const int wn = wid / WARPS_M;
    const int gid = lane >> 2;
    const int tig = lane & 3;

    const __half* Ab = A + (size_t)mbase * KldA;
    const __half* Bb = Bm + (size_t)n0 * KldB;

    float d[2][NB][4];
#pragma unroll
    for (int f = 0; f < 2; f++)
#pragma unroll
        for (int nb = 0; nb < NB; nb++)
#pragma unroll
            for (int c = 0; c < 4; c++) d[f][nb][c] = 0.0f;

    const int lr = tid >> 3;
    const int lj = tid & 7;
    auto cp_chunk = [&](int st, int k0) {
        uint32_t abase = sm_sh + (uint32_t)st * CH * 4;
#pragma unroll
        for (int it = 0; it < BM / 32; it++) {
            int r = lr + it * 32;
            cp16(abase + (uint32_t)(r * PAD + lj * 4) * 4,
                 Ab + (size_t)r * KldA + k0 + lj * 8);
        }
        uint32_t bbase = abase + BM * PAD * 4;
#pragma unroll
        for (int it = 0; it < BN / 32; it++) {
            int r = lr + it * 32;
            cp16(bbase + (uint32_t)(r * PAD + lj * 4) * 4,
                 Bb + (size_t)r * KldB + k0 + lj * 8);
        }
    };

#pragma unroll
    for (int i = 0; i < STG - 1; i++) {
        if (i < NC) cp_chunk(i, i * BKH);
        CP_COMMIT();
    }

    const int pa_off = (wm * 32 + gid) * PAD + tig;
    const int pb_off = (wn * WN + gid) * PAD + tig;

    int st = 0;
    for (int i = 0; i < NC; i++) {
        CP_WAIT2();
        __syncthreads();

        const uint32_t* sa = sm + st * CH + pa_off;
        const uint32_t* sb = sm + st * CH + BM * PAD + pb_off;

#pragma unroll
        for (int s = 0; s < 4; s++) {
            const int ko = s * 8;
            uint32_t a[2][4];
#pragma unroll
            for (int f = 0; f < 2; f++) {
                const uint32_t* q = sa + f * (16 * PAD) + ko;
                a[f][0] = q[0];
                a[f][1] = q[8 * PAD];
                a[f][2] = q[4];
                a[f][3] = q[8 * PAD + 4];
            }
            uint32_t b[NB][2];
#pragma unroll
            for (int nb = 0; nb < NB; nb++) {
                const uint32_t* q = sb + nb * (8 * PAD) + ko;
                b[nb][0] = q[0];
                b[nb][1] = q[4];
            }
#pragma unroll
            for (int f = 0; f < 2; f++)
#pragma unroll
                for (int nb = 0; nb < NB; nb++)
                    mma_f16(d[f][nb], a[f], b[nb]);
        }

        const int nx = i + STG - 1;
        if (nx < NC) cp_chunk(nx % STG, nx * BKH);
        CP_COMMIT();
        if (++st == STG) st = 0;
    }

    // ---- epilogue (fp32) ----
#pragma unroll
    for (int f = 0; f < 2; f++) {
        int m0 = mbase + wm * 32 + f * 16 + gid;
        int m1 = m0 + 8;
        float* row0;
        float* row1;
        if (OUT_MODE == 0) {
            row0 = C + (size_t)m0 * Nld;
            row1 = C + (size_t)m1 * Nld;
        } else {
            row0 = C + (size_t)((m0 & 63) * BB + (m0 >> 6)) * Nld;
            row1 = C + (size_t)((m1 & 63) * BB + (m1 >> 6)) * Nld;
        }
#pragma unroll
        for (int nb = 0; nb < NB; nb++) {
            int cn = n0 + wn * WN + nb * 8 + 2 * tig;
            float2 bb = make_float2(0.f, 0.f);
            if (bias) bb = *(const float2*)(bias + cn);
            float2 a0 = make_float2(0.f, 0.f), a1 = make_float2(0.f, 0.f);
            if (addm) {
                a0 = *(const float2*)(addm + (size_t)m0 * Nld + cn);
                a1 = *(const float2*)(addm + (size_t)m1 * Nld + cn);
            }
            float2 o0 = make_float2(d[f][nb][0] + bb.x + a0.x, d[f][nb][1] + bb.y + a0.y);
            float2 o1 = make_float2(d[f][nb][2] + bb.x + a1.x, d[f][nb][3] + bb.y + a1.y);
            *(float2*)(row0 + cn) = o0;
            *(float2*)(row1 + cn) = o1;
        }
    }
}

// Fused independent GEMMs: grid.y 0..7 wq | 8..39 uh | 40..47 s2=src@Ws^T
__global__ __launch_bounds__(256, 2)
void gqc_mma(const __half* __restrict__ rsrc, const __half* __restrict__ rmem,
             const __half* __restrict__ rWq, const float* __restrict__ bq,
             const __half* __restrict__ rWc, const __half* __restrict__ rWout,
             float* __restrict__ wq, float* __restrict__ uh,
             float* __restrict__ s2) {
    int my = blockIdx.y;
    if (my < 8)
        mma_gemm_dev<128, 64, 8, 0>(rsrc, rWq, bq, nullptr, wq,
                                    my * 128, blockIdx.x * 64, DD, DD, DD);
    else if (my < 40)
        mma_gemm_dev<128, 64, 8, 0>(rmem, rWc, nullptr, nullptr, uh,
                                    (my - 8) * 128, blockIdx.x * 64, DD, DD, DD);
    else
        mma_gemm_dev<128, 64, 8, 0>(rsrc, rWout + DD, nullptr, nullptr, s2,
                                    (my - 40) * 128, blockIdx.x * 64, DD, DD, 2 * DD);
}

// Output GEMM (c part, K=512): c(fp16) @ Wc_out^T + s2 + bias -> (T,B,D)
__global__ __launch_bounds__(256, 2)
void gout_mma(const __half* __restrict__ cc, const __half* __restrict__ rWout,
              const float* __restrict__ bout, const float* __restrict__ s2,
              float* __restrict__ out) {
    mma_gemm_dev<64, 64, 8, 1>(cc, rWout, bout, s2, out,
                               blockIdx.y * 64, blockIdx.x * 64, DD, DD, 2 * DD);
}

// ---------------------------------------------------------------------------
// Align + sparsemax (Michelot) + context with ballot-compacted support list.
// 4 t's per block, 256 CTAs, float4 score loop. cc written fp16.
// Compaction keeps ascending s order -> context summation order identical to
// the full loop -> bit-identical output.
// ---------------------------------------------------------------------------
__global__ __launch_bounds__(256)
void align4_kernel(const float* __restrict__ wq, const float* __restrict__ uh,
                   const float* __restrict__ mem, const int* __restrict__ mask,
                   const float* __restrict__ v,
                   float* __restrict__ out_align, __half* __restrict__ cc) {
    __shared__ float s_wq[4][DD];
    __shared__ float s_v[DD];
    __shared__ float s_z[4][SS];
    __shared__ float s_p[4][SS];
    __shared__ int s_mk[SS];
    __shared__ float s_red[4][2][2];
    __shared__ int s_act[SS];
    __shared__ int s_woff[9];

    const int tid = threadIdx.x;
    const int b  = blockIdx.x >> 4;
    const int t0 = (blockIdx.x & 15) * 4;

    for (int i = tid; i < 4 * DD; i += 256) {
        int tt = i >> 9, d = i & 511;
        s_wq[tt][d] = wq[((size_t)(b * TT + t0 + tt)) * DD + d];
    }
    s_v[tid] = v[tid];
    s_v[tid + 256] = v[tid + 256];
    s_mk[tid] = mask[b * SS + tid];
    __syncthreads();

    const int warp = tid >> 5, lane = tid & 31;
    for (int s = warp; s < SS; s += 8) {
        if (!s_mk[s]) {
            if (lane == 0) {
                s_z[0][s] = -1e9f; s_z[1][s] = -1e9f;
                s_z[2][s] = -1e9f; s_z[3][s] = -1e9f;
            }
            continue;
        }
        const float4* uhr = (const float4*)(uh + ((size_t)(b * SS + s)) * DD);
        float a0 = 0.f, a1 = 0.f, a2 = 0.f, a3 = 0.f;
#pragma unroll
        for (int i = 0; i < 4; i++) {
            int d4 = lane + 32 * i;
            float4 u = uhr[d4];
            float4 vv = *(const float4*)&s_v[d4 * 4];
            float4 w0 = *(const float4*)&s_wq[0][d4 * 4];
            float4 w1 = *(const float4*)&s_wq[1][d4 * 4];
            float4 w2 = *(const float4*)&s_wq[2][d4 * 4];
            float4 w3 = *(const float4*)&s_wq[3][d4 * 4];
            a0 += vv.x * htanh(w0.x + u.x) + vv.y * htanh(w0.y + u.y)
                + vv.z * htanh(w0.z + u.z) + vv.w * htanh(w0.w + u.w);
            a1 += vv.x * htanh(w1.x + u.x) + vv.y * htanh(w1.y + u.y)
                + vv.z * htanh(w1.z + u.z) + vv.w * htanh(w1.w + u.w);
            a2 += vv.x * htanh(w2.x + u.x) + vv.y * htanh(w2.y + u.y)
                + vv.z * htanh(w2.z + u.z) + vv.w * htanh(w2.w + u.w);
            a3 += vv.x * htanh(w3.x + u.x) + vv.y * htanh(w3.y + u.y)
                + vv.z * htanh(w3.z + u.z) + vv.w * htanh(w3.w + u.w);
        }
#pragma unroll
        for (int off = 16; off; off >>= 1) {
            a0 += __shfl_xor_sync(0xffffffffu, a0, off);
            a1 += __shfl_xor_sync(0xffffffffu, a1, off);
            a2 += __shfl_xor_sync(0xffffffffu, a2, off);
            a3 += __shfl_xor_sync(0xffffffffu, a3, off);
        }
        if (lane == 0) {
            s_z[0][s] = a0; s_z[1][s] = a1; s_z[2][s] = a2; s_z[3][s] = a3;
        }
    }
    __syncthreads();

    // ---- sparsemax via Michelot, 4 rows concurrently (64 threads/row) ----
    {
        const int tt = tid >> 6;
        const int u  = tid & 63;
        const int lw = (tid >> 5) & 1;
        float z[4];
        bool act[4];
#pragma unroll
        for (int j = 0; j < 4; j++) {
            z[j] = s_z[tt][u + 64 * j];
            act[j] = true;
        }
        float tau = 0.0f;
        int prev = -1;
        for (int it = 0; it < 260; it++) {
            float sv = 0.f, cv = 0.f;
#pragma unroll
            for (int j = 0; j < 4; j++)
                if (act[j]) { sv += z[j]; cv += 1.0f; }
#pragma unroll
            for (int off = 16; off; off >>= 1) {
                sv += __shfl_xor_sync(0xffffffffu, sv, off);
                cv += __shfl_xor_sync(0xffffffffu, cv, off);
            }
            if (lane == 0) { s_red[tt][lw][0] = sv; s_red[tt][lw][1] = cv; }
            BAR64(1 + tt);
            float ts = s_red[tt][0][0] + s_red[tt][1][0];
            float tc = s_red[tt][0][1] + s_red[tt][1][1];
            BAR64(1 + tt);
            int c = (int)tc;
            if (c == prev) break;
            tau = (ts - 1.0f) / tc;
            prev = c;
#pragma unroll
            for (int j = 0; j < 4; j++) act[j] = z[j] > tau;
        }
#pragma unroll
        for (int j = 0; j < 4; j++) {
            float p = fmaxf(z[j] - tau, 0.0f);
            s_p[tt][u + 64 * j] = p;
            out_align[((size_t)(t0 + tt) * BB + b) * SS + u + 64 * j] = p;
        }
    }
    __syncthreads();

    // ---- compact active-s list (ascending order; deterministic) ----
    {
        bool f = (s_p[0][tid] + s_p[1][tid] + s_p[2][tid] + s_p[3][tid]) != 0.0f;
        uint32_t bal = __ballot_sync(0xffffffffu, f);
        if (lane == 0) s_woff[warp] = __popc(bal);
        __syncthreads();
        if (tid == 0) {
            int run = 0;
#pragma unroll
            for (int w = 0; w < 8; w++) {
                int c = s_woff[w];
                s_woff[w] = run;
                run += c;
            }
            s_woff[8] = run;
        }
        __syncthreads();
        if (f) {
            int pos = s_woff[warp] + __popc(bal & ((1u << lane) - 1u));
            s_act[pos] = tid;
        }
    }
    __syncthreads();
    const int n_act = s_woff[8];

    // ---- context vectors over the compacted support union ----
    const int d0 = tid, d1 = tid + 256;
    const float* memb = mem + (size_t)b * SS * DD;
    float c00 = 0.f, c01 = 0.f, c10 = 0.f, c11 = 0.f;
    float c20 = 0.f, c21 = 0.f, c30 = 0.f, c31 = 0.f;
    for (int i = 0; i < n_act; i++) {
        int s = s_act[i];
        float p0 = s_p[0][s], p1 = s_p[1][s], p2 = s_p[2][s], p3 = s_p[3][s];
        const float* row = memb + (size_t)s * DD;
        float r0 = row[d0], r1 = row[d1];
        c00 = fmaf(p0, r0, c00); c01 = fmaf(p0, r1, c01);
        c10 = fmaf(p1, r0, c10); c11 = fmaf(p1, r1, c11);
        c20 = fmaf(p2, r0, c20); c21 = fmaf(p2, r1, c21);
        c30 = fmaf(p3, r0, c30); c31 = fmaf(p3, r1, c31);
    }
    float cc0[4] = {c00, c10, c20, c30};
    float cc1[4] = {c01, c11, c21, c31};
#pragma unroll
    for (int tt = 0; tt < 4; tt++) {
        __half* crow = cc + (size_t)(b * TT + t0 + tt) * DD;
        crow[d0] = __float2half_rn(cc0[tt]);
        crow[d1] = __float2half_rn(cc1[tt]);
    }
}

// ---------------------------------------------------------------------------
extern "C" void kernel_launch(void* const* d_in, const int* in_sizes, int n_in,
                              void* d_out, int out_size) {
    const float* source      = (const float*)d_in[0];
    const float* memory_bank = (const float*)d_in[1];
    const int*   memory_mask = (const int*)d_in[2];
    const float* W_q         = (const float*)d_in[3];
    const float* b_q         = (const float*)d_in[4];
    const float* W_c         = (const float*)d_in[5];
    const float* v           = (const float*)d_in[6];
    const float* W_out       = (const float*)d_in[7];
    const float* b_out       = (const float*)d_in[8];

    float* out       = (float*)d_out;
    float* out_attn  = out;                         // (T,B,D)
    float* out_align = out + (size_t)TT * BB * DD;  // (T,B,S)

    float *p_wq, *p_uh, *p_s2;
    __half *p_cc, *p_rsrc, *p_rmem, *p_rwq, *p_rwc, *p_rwout;
    cudaGetSymbolAddress((void**)&p_wq, g_wq);
    cudaGetSymbolAddress((void**)&p_uh, g_uh);
    cudaGetSymbolAddress((void**)&p_cc, g_cc);
    cudaGetSymbolAddress((void**)&p_s2, g_s2);
    cudaGetSymbolAddress((void**)&p_rsrc, g_rsrc);
    cudaGetSymbolAddress((void**)&p_rmem, g_rmem);
    cudaGetSymbolAddress((void**)&p_rwq, g_rwq);
    cudaGetSymbolAddress((void**)&p_rwc, g_rwc);
    cudaGetSymbolAddress((void**)&p_rwout, g_rwout);

    const int smem_qc  = 4 * (128 + 64) * 36 * 4;  // 110592
    const int smem_out = 4 * (64 + 64) * 36 * 4;   // 73728
    cudaFuncSetAttribute(gqc_mma, cudaFuncAttributeMaxDynamicSharedMemorySize, smem_qc);
    cudaFuncSetAttribute(gout_mma, cudaFuncAttributeMaxDynamicSharedMemorySize, smem_out);

    // 0) fp32 -> fp16 conversion of all GEMM inputs
    round_kernel<<<3584, 256>>>(source, memory_bank, W_q, W_c, W_out,
                                p_rsrc, p_rmem, p_rwq, p_rwc, p_rwout);

    // 1) wq, uh, s2 (fp16 mma.sync k16 + cp.async): 384 CTAs
    gqc_mma<<<dim3(8, 48), 256, smem_qc>>>(
        p_rsrc, p_rmem, p_rwq, b_q, p_rwc, p_rwout, p_wq, p_uh, p_s2);

    // 2) align + sparsemax + context: 256 CTAs (4 t's each)
    align4_kernel<<<BB * (TT / 4), 256>>>(
        p_wq, p_uh, memory_bank, memory_mask, v, out_align, p_cc);

    // 3) attn_h = c @ Wc^T + s2 + bias -> (T,B,D): 128 CTAs, K=512
    gout_mma<<<dim3(8, 16), 256, smem_out>>>(p_cc, p_rwout, b_out, p_s2, out_attn);
}